// round 8
// baseline (speedup 1.0000x reference)
#include <cuda_runtime.h>

// WOS 3x3 filter — key-only sorting network + warp-uniform tie fast path,
// trimmed key build (fused LOPs) and trimmed fast epilogue (no per-element
// nonzero test when the block-staged "tiny weight" flag is clear).
//
// key = (sortable_fp32(mx) | 63) ^ (63 ^ slot)  == (sortable & ~63) | slot
// Fast path (no adjacent 26-bit key collision in warp AND no weight <= tol):
// key order == exact value order, all weights participate -> cumsum identical
// to reference. Otherwise: full-precision adjacent-pair repair with nz checks
// (R6 logic, proven rel_err 0.0).

#define NCH 16
#define DD 54
#define HH 64
#define WW 64
#define PIX_PER_BLK 8
#define NTHREADS (NCH * PIX_PER_BLK)   // 128
#define TILE_COLS (PIX_PER_BLK + 2)    // 10
#define TILE_ELEMS (3 * 3 * TILE_COLS) // 90
#define VSTRIDE 55                     // per-thread value row (slots 10..63)
#define WSTRIDE 65                     // per-channel weight row
#define ZTOL 1e-6f

__global__ __launch_bounds__(NTHREADS, 6)
void wos_kernel(const float* __restrict__ x,
                const float* __restrict__ mask,
                const float* __restrict__ weight,
                const float* __restrict__ bias,
                float* __restrict__ out)
{
    __shared__ float tile_s[TILE_ELEMS];
    __shared__ float msk_s[NCH * DD];
    __shared__ float w2_s[NCH * WSTRIDE];          // slot-indexed weights
    __shared__ float bias_s[NCH];
    __shared__ int   tiny_s;                       // any weight <= ZTOL?
    __shared__ float vst_s[NTHREADS * VSTRIDE];    // per-thread exact mx values

    const int tid = threadIdx.x;
    const int c  = tid & (NCH - 1);
    const int ty = tid >> 4;

    const int pix0 = blockIdx.x * PIX_PER_BLK;
    const int b    = pix0 >> 12;
    const int rem  = pix0 & 4095;
    const int h    = rem >> 6;
    const int w0   = rem & 63;

    if (tid == 0) tiny_s = 0;

    // ---- cooperative staging ----
    #pragma unroll
    for (int idx = tid; idx < NCH * DD; idx += NTHREADS) {
        const int cw = idx / DD;
        const int d  = idx - cw * DD;
        const float wgt = weight[idx];
        msk_s[idx] = mask[idx];
        w2_s[cw * WSTRIDE + (53 - d)] = wgt;       // slot 63-d at offset-10
        if (wgt <= ZTOL) tiny_s = 1;
    }
    if (tid < NCH) bias_s[tid] = bias[tid];
    for (int idx = tid; idx < TILE_ELEMS; idx += NTHREADS) {
        int cc  = idx / (3 * TILE_COLS);
        int r   = (idx / TILE_COLS) % 3;
        int col = idx % TILE_COLS;
        int gh = h + r - 1;
        int gw = w0 + col - 1;
        float v = 0.0f;
        if (gh >= 0 && gh < HH && gw >= 0 && gw < WW)
            v = x[((b * 3 + cc) * HH + gh) * WW + gw];
        tile_s[idx] = v;
    }
    __syncthreads();

    const float* wrow = &w2_s[c * WSTRIDE] - 10;   // index by slot in [10,63]
    float*       vrow = &vst_s[tid * VSTRIDE] - 10;
    const float* mrow = &msk_s[c * DD];
    const bool   tinyw = (tiny_s != 0);

    // ---- build keys (regs) + exact values (smem) ----
    unsigned key[DD];
    #pragma unroll
    for (int d0 = 0; d0 < 27; d0++) {
        const int cc = d0 / 9;
        const int r  = (d0 / 3) % 3;
        const int j  = d0 % 3;
        float t  = tile_s[(cc * 3 + r) * TILE_COLS + ty + j];
        float fp = t + mrow[d0];            // element d0    -> slot 63-d0
        float fm = mrow[27 + d0] - t;       // element 27+d0 -> slot 36-d0
        vrow[63 - d0] = fp;
        vrow[36 - d0] = fm;
        // sortable transform: 2 ops (SHF + fused LOP3)
        unsigned up = __float_as_uint(fp);
        unsigned sp = up ^ (((unsigned)(((int)up) >> 31)) | 0x80000000u);
        unsigned um = __float_as_uint(fm);
        unsigned sm = um ^ (((unsigned)(((int)um) >> 31)) | 0x80000000u);
        // (s & ~63) | slot == (s | 63) ^ (63 ^ slot): 2 LOPs with immediates
        key[d0]      = (sp | 63u) ^ (63u ^ (unsigned)(63 - d0));
        key[27 + d0] = (sm | 63u) ^ (63u ^ (unsigned)(36 - d0));
    }

    // ---- Batcher odd-even merge sort, descending, n=54, key-only CEs ----
#define CE(A, B)                                 \
    do {                                         \
        unsigned ka = key[A], kb = key[B];       \
        key[A] = umax(ka, kb);                   \
        key[B] = umin(ka, kb);                   \
    } while (0)

#define PASS(P, K)                                                          \
    _Pragma("unroll")                                                       \
    for (int j = (K) % (P); j + (K) < DD; j += 2 * (K)) {                   \
        _Pragma("unroll")                                                   \
        for (int i = 0; i < (K); i++) {                                     \
            const int a  = i + j;                                           \
            const int bb = i + j + (K);                                     \
            if (bb < DD && (a / (2 * (P))) == (bb / (2 * (P))))             \
                CE(a, bb);                                                  \
        }                                                                   \
    }

    PASS(1, 1)
    PASS(2, 2)  PASS(2, 1)
    PASS(4, 4)  PASS(4, 2)  PASS(4, 1)
    PASS(8, 8)  PASS(8, 4)  PASS(8, 2)  PASS(8, 1)
    PASS(16, 16) PASS(16, 8) PASS(16, 4) PASS(16, 2) PASS(16, 1)
    PASS(32, 32) PASS(32, 16) PASS(32, 8) PASS(32, 4) PASS(32, 2) PASS(32, 1)

#undef PASS
#undef CE

    // ---- tie detection: any adjacent pair sharing top-26 key bits? ----
    unsigned tmin = 0xFFFFFFFFu;
    #pragma unroll
    for (int k2 = 0; k2 < DD - 1; k2++)
        tmin = umin(tmin, key[k2] ^ key[k2 + 1]);
    const bool slow = __any_sync(0xFFFFFFFFu, tmin < 64u) | tinyw;

    const float bs = bias_s[c];
    float y;

    if (!slow) {
        // ---- fast path (exact): all weights nonzero, key order exact ----
        float acc = 0.0f;
        unsigned selk = key[0];
        #pragma unroll
        for (int k2 = 0; k2 < DD; k2++) {
            const unsigned ck = key[k2];
            acc += wrow[ck & 63u];
            if (acc <= bs) selk = ck;
        }
        y = vrow[selk & 63u];
    } else {
        // ---- repair path: full-precision adjacent-tie repair + nz checks ----
        float acc = 0.0f;
        float ans = 0.0f;
        bool  seen = false;
        unsigned pk = key[0];
        float pv = vrow[pk & 63u];
        float pw = wrow[pk & 63u];

        #pragma unroll
        for (int k2 = 1; k2 < DD; k2++) {
            const unsigned ck = key[k2];
            const unsigned sl = ck & 63u;
            const float cv = vrow[sl];
            const float cw = wrow[sl];
            const bool sw = ((pk ^ ck) < 64u) && (cv > pv);
            const float ev = sw ? cv : pv;
            const float ew = sw ? cw : pw;
            pv = sw ? pv : cv;
            pw = sw ? pw : cw;
            pk = ck;

            const bool nz = ew > ZTOL;
            if (nz) acc += ew;
            if (nz && ((acc <= bs) || !seen)) ans = ev;
            seen |= nz;
        }
        {
            const bool nz = pw > ZTOL;
            if (nz) acc += pw;
            if (nz && ((acc <= bs) || !seen)) ans = pv;
        }
        y = ans;
    }

    // raw .view(B, NC, H, W): channel fastest -> coalesced
    const int l = h * WW + (w0 + ty);
    out[b * (NCH * HH * WW) + l * NCH + c] = y;
}

extern "C" void kernel_launch(void* const* d_in, const int* in_sizes, int n_in,
                              void* d_out, int out_size)
{
    const float* x      = (const float*)d_in[0];
    const float* mask   = (const float*)d_in[1];
    const float* weight = (const float*)d_in[2];
    const float* bias   = (const float*)d_in[3];
    float* out = (float*)d_out;

    const int B = in_sizes[0] / (3 * HH * WW);
    const int npix = B * HH * WW;
    dim3 grid(npix / PIX_PER_BLK);
    wos_kernel<<<grid, NTHREADS>>>(x, mask, weight, bias, out);
}

// round 9
// speedup vs baseline: 1.0037x; 1.0037x over previous
#include <cuda_runtime.h>

// WOS 3x3 filter — key-only sorting network, NO per-thread value store.
//
// key = (sortable_fp32(mx) & ~63) | slot, slot = 63-d. umax/umin CEs.
// Values are never stored per-thread: v(d) = (d<27) ? t+mask[d] : mask[d]-t
// recomputed bit-exactly from tile_s/msk_s on demand (1 value in the fast
// path, per-element in the rare repair path). This removes the 27.6KB smem
// value array and 54 STS/thread, unlocking 7 blocks/SM.

#define NCH 16
#define DD 54
#define HH 64
#define WW 64
#define PIX_PER_BLK 8
#define NTHREADS (NCH * PIX_PER_BLK)   // 128
#define TILE_COLS (PIX_PER_BLK + 2)    // 10
#define TILE_ELEMS (3 * 3 * TILE_COLS) // 90
#define WSTRIDE 65                     // per-channel weight row
#define ZTOL 1e-6f

__global__ __launch_bounds__(NTHREADS, 7)
void wos_kernel(const float* __restrict__ x,
                const float* __restrict__ mask,
                const float* __restrict__ weight,
                const float* __restrict__ bias,
                float* __restrict__ out)
{
    __shared__ float tile_s[TILE_ELEMS];
    __shared__ float msk_s[NCH * DD];
    __shared__ float w2_s[NCH * WSTRIDE];   // slot-indexed weights
    __shared__ float bias_s[NCH];
    __shared__ int   toff_s[DD];            // tile offset per element index d
    __shared__ int   tiny_s;                // any weight <= ZTOL?

    const int tid = threadIdx.x;
    const int c  = tid & (NCH - 1);
    const int ty = tid >> 4;

    const int pix0 = blockIdx.x * PIX_PER_BLK;
    const int b    = pix0 >> 12;
    const int rem  = pix0 & 4095;
    const int h    = rem >> 6;
    const int w0   = rem & 63;

    if (tid == 0) tiny_s = 0;

    // ---- cooperative staging ----
    #pragma unroll
    for (int idx = tid; idx < NCH * DD; idx += NTHREADS) {
        const int cw = idx / DD;
        const int d  = idx - cw * DD;
        const float wgt = weight[idx];
        msk_s[idx] = mask[idx];
        w2_s[cw * WSTRIDE + (53 - d)] = wgt;   // slot 63-d stored at slot-10
        if (wgt <= ZTOL) tiny_s = 1;
    }
    if (tid < NCH) bias_s[tid] = bias[tid];
    if (tid < DD) {
        const int d0 = (tid < 27) ? tid : tid - 27;
        toff_s[tid] = ((d0 / 9) * 3 + ((d0 / 3) % 3)) * TILE_COLS + (d0 % 3);
    }
    for (int idx = tid; idx < TILE_ELEMS; idx += NTHREADS) {
        int cc  = idx / (3 * TILE_COLS);
        int r   = (idx / TILE_COLS) % 3;
        int col = idx % TILE_COLS;
        int gh = h + r - 1;
        int gw = w0 + col - 1;
        float v = 0.0f;
        if (gh >= 0 && gh < HH && gw >= 0 && gw < WW)
            v = x[((b * 3 + cc) * HH + gh) * WW + gw];
        tile_s[idx] = v;
    }
    __syncthreads();

    const float* wrow = &w2_s[c * WSTRIDE] - 10;   // index by slot in [10,63]
    const float* mrow = &msk_s[c * DD];
    const bool   tinyw = (tiny_s != 0);

    // ---- build keys (regs only) ----
    unsigned key[DD];
    #pragma unroll
    for (int d0 = 0; d0 < 27; d0++) {
        const int cc = d0 / 9;
        const int r  = (d0 / 3) % 3;
        const int j  = d0 % 3;
        float t  = tile_s[(cc * 3 + r) * TILE_COLS + ty + j];
        float fp = t + mrow[d0];            // element d0    -> slot 63-d0
        float fm = mrow[27 + d0] - t;       // element 27+d0 -> slot 36-d0
        unsigned up = __float_as_uint(fp);
        unsigned sp = up ^ (((unsigned)(((int)up) >> 31)) | 0x80000000u);
        unsigned um = __float_as_uint(fm);
        unsigned sm = um ^ (((unsigned)(((int)um) >> 31)) | 0x80000000u);
        key[d0]      = (sp & 0xFFFFFFC0u) | (unsigned)(63 - d0);
        key[27 + d0] = (sm & 0xFFFFFFC0u) | (unsigned)(36 - d0);
    }

    // ---- Batcher odd-even merge sort, descending, n=54, key-only CEs ----
#define CE(A, B)                                 \
    do {                                         \
        unsigned ka = key[A], kb = key[B];       \
        key[A] = umax(ka, kb);                   \
        key[B] = umin(ka, kb);                   \
    } while (0)

#define PASS(P, K)                                                          \
    _Pragma("unroll")                                                       \
    for (int j = (K) % (P); j + (K) < DD; j += 2 * (K)) {                   \
        _Pragma("unroll")                                                   \
        for (int i = 0; i < (K); i++) {                                     \
            const int a  = i + j;                                           \
            const int bb = i + j + (K);                                     \
            if (bb < DD && (a / (2 * (P))) == (bb / (2 * (P))))             \
                CE(a, bb);                                                  \
        }                                                                   \
    }

    PASS(1, 1)
    PASS(2, 2)  PASS(2, 1)
    PASS(4, 4)  PASS(4, 2)  PASS(4, 1)
    PASS(8, 8)  PASS(8, 4)  PASS(8, 2)  PASS(8, 1)
    PASS(16, 16) PASS(16, 8) PASS(16, 4) PASS(16, 2) PASS(16, 1)
    PASS(32, 32) PASS(32, 16) PASS(32, 8) PASS(32, 4) PASS(32, 2) PASS(32, 1)

#undef PASS
#undef CE

    // ---- tie detection (tree-reduced for ILP) ----
    unsigned t0 = 0xFFFFFFFFu, t1 = 0xFFFFFFFFu, t2 = 0xFFFFFFFFu, t3 = 0xFFFFFFFFu;
    #pragma unroll
    for (int k2 = 0; k2 + 4 <= DD - 1; k2 += 4) {
        t0 = umin(t0, key[k2]     ^ key[k2 + 1]);
        t1 = umin(t1, key[k2 + 1] ^ key[k2 + 2]);
        t2 = umin(t2, key[k2 + 2] ^ key[k2 + 3]);
        t3 = umin(t3, key[k2 + 3] ^ key[k2 + 4]);
    }
    t0 = umin(t0, key[52] ^ key[53]);   // remaining pair (k2=52)
    const unsigned tmin = umin(umin(t0, t1), umin(t2, t3));
    const bool slow = __any_sync(0xFFFFFFFFu, tmin < 64u) | tinyw;

    const float bs = bias_s[c];
    float y;

    if (!slow) {
        // ---- fast path (exact): weights only; recompute 1 value at end ----
        float acc = 0.0f;
        unsigned selk = key[0];
        #pragma unroll
        for (int k2 = 0; k2 < DD; k2++) {
            const unsigned ck = key[k2];
            acc += wrow[ck & 63u];
            if (acc <= bs) selk = ck;
        }
        const int d = 63 - (int)(selk & 63u);
        const float t = tile_s[toff_s[d] + ty];
        const float m = mrow[d];
        y = (d < 27) ? (t + m) : (m - t);
    } else {
        // ---- repair path: full-precision adjacent-tie repair + nz checks ----
        float acc = 0.0f;
        float ans = 0.0f;
        bool  seen = false;

        unsigned pk = key[0];
        int dp = 63 - (int)(pk & 63u);
        float tp = tile_s[toff_s[dp] + ty];
        float mp = mrow[dp];
        float pv = (dp < 27) ? (tp + mp) : (mp - tp);
        float pw = wrow[pk & 63u];

        #pragma unroll
        for (int k2 = 1; k2 < DD; k2++) {
            const unsigned ck = key[k2];
            const unsigned sl = ck & 63u;
            const int dc = 63 - (int)sl;
            const float tc = tile_s[toff_s[dc] + ty];
            const float mc = mrow[dc];
            const float cv = (dc < 27) ? (tc + mc) : (mc - tc);
            const float cw = wrow[sl];

            const bool sw = ((pk ^ ck) < 64u) && (cv > pv);
            const float ev = sw ? cv : pv;
            const float ew = sw ? cw : pw;
            pv = sw ? pv : cv;
            pw = sw ? pw : cw;
            pk = ck;

            const bool nz = ew > ZTOL;
            if (nz) acc += ew;
            if (nz && ((acc <= bs) || !seen)) ans = ev;
            seen |= nz;
        }
        {
            const bool nz = pw > ZTOL;
            if (nz) acc += pw;
            if (nz && ((acc <= bs) || !seen)) ans = pv;
        }
        y = ans;
    }

    // raw .view(B, NC, H, W): channel fastest -> coalesced
    const int l = h * WW + (w0 + ty);
    out[b * (NCH * HH * WW) + l * NCH + c] = y;
}

extern "C" void kernel_launch(void* const* d_in, const int* in_sizes, int n_in,
                              void* d_out, int out_size)
{
    const float* x      = (const float*)d_in[0];
    const float* mask   = (const float*)d_in[1];
    const float* weight = (const float*)d_in[2];
    const float* bias   = (const float*)d_in[3];
    float* out = (float*)d_out;

    const int B = in_sizes[0] / (3 * HH * WW);
    const int npix = B * HH * WW;
    dim3 grid(npix / PIX_PER_BLK);
    wos_kernel<<<grid, NTHREADS>>>(x, mask, weight, bias, out);
}